// round 14
// baseline (speedup 1.0000x reference)
#include <cuda_runtime.h>
#include <cuda_fp16.h>
#include <cstdint>

#define NN 113664
#define FF 128
#define EE 909312
#define TT 4
#define BB 1024
#define CC 2
#define NPG 111        // nodes per graph = NN/BB
#define NBLK 444       // NN / 256

// GEMM tiling (fp16 mma.m16n8k16), BM=64 rows/CTA, 256 threads, 2 CTAs/SM
#define BM 64
#define KC 32          // K floats per chunk (16 half2)
#define AS_STR 20      // As row stride in uints -> conflict-free frags
#define BSZ_STR 264    // Bs k2-row stride GEMM1 (n=256)
#define BSC_STR 136    // Bs k2-row stride GEMM2 (n=128)
#define HRH 136        // hr fp16 smem stride (halves)
#define ZSH 136        // z  fp16 smem stride (halves)
// smem ring geometry (uint units)
#define AS_STAGE (BM * AS_STR)       // 1280
#define BS_STAGE (16 * BSZ_STR)      // 4224
#define AS_TOT (3 * AS_STAGE)        // 3840
#define BS_TOT (3 * BS_STAGE)        // 12672

// ---------------- device scratch (static: no runtime allocation) ----------------
__device__ float g_dinv[TT * NN];
__device__ int   g_cnt [TT * NN];
__device__ int   g_rowptr[TT * (NN + 1)];
__device__ int   g_cursor[TT * NN];
__device__ int   g_bsum[TT * NBLK];
__device__ int   g_boff[TT * (NBLK + 1)];
__device__ int2  g_cv[TT * EE];          // packed (col, val-bits) per edge
__device__ __half g_xh [TT * NN * FF];   // fp16 copy of xs
__device__ __half g_axh[TT * NN * FF];   // fp16 aggregated features
__device__ __half g_hh [NN * FF];        // fp16 hidden state
__device__ float g_out[NN * FF];
__device__ unsigned g_Wzr[128 * 256];   // half2 packed [k2][n]: n<128:z n>=128:r
__device__ unsigned g_Whc[128 * 128];   // half2 packed [k2][n]
__device__ float g_bias_zr[256];
__device__ float g_bias_c[128];

// ---------------- math helpers ----------------
__device__ __forceinline__ float tanh_fast(float x) {
    float y;
    asm("tanh.approx.f32 %0, %1;" : "=f"(y) : "f"(x));
    return y;
}
__device__ __forceinline__ float sigmoid_fast(float x) {
    return 0.5f * tanh_fast(0.5f * x) + 0.5f;
}
__device__ __forceinline__ unsigned pkh2(float a, float b) {
    __half2 h = __float22half2_rn(make_float2(a, b));
    return *reinterpret_cast<unsigned*>(&h);
}
__device__ __forceinline__ void mma_f16(float d[4], const unsigned a[4], const unsigned b[2]) {
    asm volatile(
        "mma.sync.aligned.m16n8k16.row.col.f32.f16.f16.f32 "
        "{%0,%1,%2,%3}, {%4,%5,%6,%7}, {%8,%9}, {%0,%1,%2,%3};"
        : "+f"(d[0]), "+f"(d[1]), "+f"(d[2]), "+f"(d[3])
        : "r"(a[0]), "r"(a[1]), "r"(a[2]), "r"(a[3]), "r"(b[0]), "r"(b[1]));
}
__device__ __forceinline__ uint32_t smem_u32(const void* p) {
    uint32_t a;
    asm("{ .reg .u64 t; cvta.to.shared.u64 t, %1; cvt.u32.u64 %0, t; }" : "=r"(a) : "l"(p));
    return a;
}
__device__ __forceinline__ void cpa16(uint32_t dst, const void* src) {
    asm volatile("cp.async.cg.shared.global [%0], [%1], 16;" :: "r"(dst), "l"(src));
}
#define CP_COMMIT() asm volatile("cp.async.commit_group;" ::: "memory")
#define CP_WAIT(n)  asm volatile("cp.async.wait_group %0;" :: "n"(n) : "memory")

// ---------------- init: hh = eye(N,F) fp16, out = 0 ----------------
__global__ void k_init_hout() {
    int idx = blockIdx.x * blockDim.x + threadIdx.x;
    if (idx >= NN * FF / 4) return;
    reinterpret_cast<float4*>(g_out)[idx] = make_float4(0.f, 0.f, 0.f, 0.f);
    if (idx < NN * FF / 8) {
        int base = idx * 8;
        int row = base >> 7;
        int c0 = base & 127;
        __half h8[8];
#pragma unroll
        for (int u = 0; u < 8; u++) h8[u] = __float2half(0.f);
        if (row < FF && row >= c0 && row < c0 + 8) h8[row - c0] = __float2half(1.f);
        reinterpret_cast<uint4*>(g_hh)[idx] = *reinterpret_cast<uint4*>(h8);
    }
}

// ---------------- xs (slice t) -> fp16 ----------------
__global__ void k_h16(int t, const float* __restrict__ xs) {
    int idx = blockIdx.x * blockDim.x + threadIdx.x;   // uint4 index within slice
    if (idx >= NN * FF / 8) return;
    const float4* src = reinterpret_cast<const float4*>(xs + (size_t)t * NN * FF) + idx * 2;
    float4 v0 = __ldg(src), v1 = __ldg(src + 1);
    uint4 o = make_uint4(pkh2(v0.x, v0.y), pkh2(v0.z, v0.w),
                         pkh2(v1.x, v1.y), pkh2(v1.z, v1.w));
    reinterpret_cast<uint4*>(g_xh + (size_t)t * NN * FF)[idx] = o;
}

// ---------------- weight packing: half2 [k2][n] + fused biases ----------------
__global__ void k_pack(const float* __restrict__ Wzi, const float* __restrict__ bzi,
                       const float* __restrict__ Wzh, const float* __restrict__ bzh,
                       const float* __restrict__ Wri, const float* __restrict__ bri,
                       const float* __restrict__ Wrh, const float* __restrict__ brh,
                       const float* __restrict__ Whi, const float* __restrict__ bhi,
                       const float* __restrict__ Whh, const float* __restrict__ bhh) {
    int i = blockIdx.x * blockDim.x + threadIdx.x;
    if (i < 32768) {                       // g_Wzr: [k2=0..127][n=0..255]
        int k2 = i >> 8, n = i & 255;
        int k = 2 * k2;
        float v0, v1;
        if (k < 128) {
            v0 = (n < 128) ? Wzi[k * 128 + n]       : Wri[k * 128 + (n - 128)];
            v1 = (n < 128) ? Wzi[(k + 1) * 128 + n] : Wri[(k + 1) * 128 + (n - 128)];
        } else {
            int kk = k - 128;
            v0 = (n < 128) ? Wzh[kk * 128 + n]       : Wrh[kk * 128 + (n - 128)];
            v1 = (n < 128) ? Wzh[(kk + 1) * 128 + n] : Wrh[(kk + 1) * 128 + (n - 128)];
        }
        g_Wzr[i] = pkh2(v0, v1);
    } else if (i < 32768 + 16384) {        // g_Whc: [k2=0..127][n=0..127]
        int j = i - 32768;
        int k2 = j >> 7, n = j & 127;
        int k = 2 * k2;
        float v0, v1;
        if (k < 128) { v0 = Whi[k * 128 + n]; v1 = Whi[(k + 1) * 128 + n]; }
        else { int kk = k - 128; v0 = Whh[kk * 128 + n]; v1 = Whh[(kk + 1) * 128 + n]; }
        g_Whc[j] = pkh2(v0, v1);
    } else if (i < 32768 + 16384 + 256) {
        int n = i - (32768 + 16384);
        g_bias_zr[n] = (n < 128) ? (bzi[n] + bzh[n]) : (bri[n - 128] + brh[n - 128]);
    } else if (i < 32768 + 16384 + 384) {
        int n = i - (32768 + 16384 + 256);
        g_bias_c[n] = bhi[n] + bhh[n];
    }
}

// ---------------- per-step CSR build ----------------
__global__ void k_prep(int t) {
    int i = blockIdx.x * blockDim.x + threadIdx.x;
    if (i < NN) g_cnt[t * NN + i] = 0;
}

__global__ void k_cnt(int t, const int* __restrict__ eis) {
    int e = blockIdx.x * blockDim.x + threadIdx.x;
    if (e >= EE) return;
    int d = eis[(size_t)t * 2 * EE + EE + e];
    atomicAdd(&g_cnt[t * NN + d], 1);
}

__global__ void k_scan1(int t) {
    __shared__ int sh[256];
    int tid = threadIdx.x;
    sh[tid] = g_cnt[t * NN + blockIdx.x * 256 + tid];
    __syncthreads();
#pragma unroll
    for (int off = 128; off > 0; off >>= 1) {
        if (tid < off) sh[tid] += sh[tid + off];
        __syncthreads();
    }
    if (tid == 0) g_bsum[t * NBLK + blockIdx.x] = sh[0];
}

__global__ void k_scan2(int t) {
    __shared__ int sh[512];
    int tid = threadIdx.x;
    int v = (tid < NBLK) ? g_bsum[t * NBLK + tid] : 0;
    sh[tid] = v;
    __syncthreads();
#pragma unroll
    for (int off = 1; off < 512; off <<= 1) {
        int u = (tid >= off) ? sh[tid - off] : 0;
        __syncthreads();
        sh[tid] += u;
        __syncthreads();
    }
    if (tid < NBLK) g_boff[t * (NBLK + 1) + tid] = sh[tid] - v;
    if (tid == NBLK - 1) g_boff[t * (NBLK + 1) + NBLK] = sh[tid];
}

__global__ void k_scan3(int t) {
    __shared__ int sh[256];
    int tid = threadIdx.x;
    int i = blockIdx.x * 256 + tid;
    int c = g_cnt[t * NN + i];
    sh[tid] = c;
    __syncthreads();
#pragma unroll
    for (int off = 1; off < 256; off <<= 1) {
        int u = (tid >= off) ? sh[tid - off] : 0;
        __syncthreads();
        sh[tid] += u;
        __syncthreads();
    }
    int excl = sh[tid] - c + g_boff[t * (NBLK + 1) + blockIdx.x];
    g_rowptr[t * (NN + 1) + i] = excl;
    g_cursor[t * NN + i] = excl;
    if (i == NN - 1) g_rowptr[t * (NN + 1) + NN] = excl + c;
}

__global__ void k_fill(int t, const float* __restrict__ eas, const int* __restrict__ eis) {
    int e = blockIdx.x * blockDim.x + threadIdx.x;
    if (e >= EE) return;
    int s = eis[(size_t)t * 2 * EE + e];
    int d = eis[(size_t)t * 2 * EE + EE + e];
    int pos = atomicAdd(&g_cursor[t * NN + d], 1);
    g_cv[(size_t)t * EE + pos] = make_int2(s, __float_as_int(eas[(size_t)t * EE + e]));
}

__global__ void k_deg(int t) {
    int i = blockIdx.x * blockDim.x + threadIdx.x;
    if (i >= NN) return;
    int beg = g_rowptr[t * (NN + 1) + i], end = g_rowptr[t * (NN + 1) + i + 1];
    const int2* cv = g_cv + (size_t)t * EE;
    float s = 1.0f;
    for (int j = beg; j < end; j++) s += __int_as_float(cv[j].y);
    g_dinv[t * NN + i] = rsqrtf(s);
}

__global__ void k_norm(int t) {
    int e = blockIdx.x * blockDim.x + threadIdx.x;
    if (e >= EE) return;
    int2 cv = g_cv[(size_t)t * EE + e];
    cv.y = __float_as_int(__int_as_float(cv.y) * g_dinv[t * NN + cv.x]);
    g_cv[(size_t)t * EE + e] = cv;
}

// ---------------- sparse aggregate (fp16 gather, lane-parallel edge read) ----------------
__global__ void k_agg(int t) {
    int gw = (blockIdx.x * blockDim.x + threadIdx.x) >> 5;
    if (gw >= NN) return;
    int lane = threadIdx.x & 31;

    const __half* x = g_xh + (size_t)t * NN * FF;
    float dinv_d = g_dinv[t * NN + gw];
    float self = dinv_d * dinv_d;

    uint2 raw = __ldg(reinterpret_cast<const uint2*>(x + (size_t)gw * FF) + lane);
    float2 xv0 = __half22float2(*reinterpret_cast<const __half2*>(&raw.x));
    float2 xv1 = __half22float2(*reinterpret_cast<const __half2*>(&raw.y));

    float4 a = make_float4(0.f, 0.f, 0.f, 0.f);
    int beg = g_rowptr[t * (NN + 1) + gw], end = g_rowptr[t * (NN + 1) + gw + 1];
    const int2* cvp = g_cv + (size_t)t * EE;

    for (int base = beg; base < end; base += 32) {
        int j = base + lane;
        int2 cv = (j < end) ? __ldg(cvp + j) : make_int2(0, 0);
        int cnt = min(32, end - base);
        for (int k = 0; k < cnt; k++) {
            int   s = __shfl_sync(0xffffffffu, cv.x, k);
            float v = __int_as_float(__shfl_sync(0xffffffffu, cv.y, k));
            uint2 rw = __ldg(reinterpret_cast<const uint2*>(x + (size_t)s * FF) + lane);
            float2 f0 = __half22float2(*reinterpret_cast<const __half2*>(&rw.x));
            float2 f1 = __half22float2(*reinterpret_cast<const __half2*>(&rw.y));
            a.x += v * f0.x; a.y += v * f0.y; a.z += v * f1.x; a.w += v * f1.y;
        }
    }
    a.x = dinv_d * a.x + self * xv0.x;
    a.y = dinv_d * a.y + self * xv0.y;
    a.z = dinv_d * a.z + self * xv1.x;
    a.w = dinv_d * a.w + self * xv1.y;
    uint2 w;
    w.x = pkh2(a.x, a.y);
    w.y = pkh2(a.z, a.w);
    reinterpret_cast<uint2*>(g_axh + (size_t)t * NN * FF + (size_t)gw * FF)[lane] = w;
}

// ================= Fused GRU step: cp.async 3-stage pipeline, fp16 state =================
__global__ void __launch_bounds__(256, 2) k_gru(int step) {
    extern __shared__ unsigned sm[];
    unsigned* As = sm;                       // 3 stages x [64][AS_STR]
    unsigned* Bs = sm + AS_TOT;              // 3 stages x [16][BSZ_STR]
    __half* hr_h = reinterpret_cast<__half*>(sm + AS_TOT + BS_TOT);   // [64][HRH]
    __half* z_h  = hr_h + BM * HRH;                                   // [64][ZSH]

    const uint32_t as_b = smem_u32(As);
    const uint32_t bs_b = smem_u32(Bs);

    const __half* axh = g_axh + (size_t)step * NN * FF;
    const int tid = threadIdx.x;
    const int w = tid >> 5, lane = tid & 31;
    const int wm = w & 1, wn = w >> 1;
    const int gid = lane >> 2, tig = lane & 3;
    const int row0 = blockIdx.x * BM;
    const int ar = tid >> 2, aq = tid & 3;

    const uint32_t a_dst0 = as_b + (uint32_t)(ar * AS_STR + aq * 4) * 4;

    // ---------------- GEMM1: N=256 ----------------
    {
        float acc[2][8][4];
#pragma unroll
        for (int mt = 0; mt < 2; mt++)
#pragma unroll
            for (int nt = 0; nt < 8; nt++)
#pragma unroll
                for (int q = 0; q < 4; q++) acc[mt][nt][q] = 0.f;

#define STAGE1(c) do { \
        int s_ = (c) % 3; \
        const __half* Asrc_ = (((c) < 4) ? axh : g_hh) + (size_t)(row0 + ar) * FF + ((c) & 3) * KC; \
        cpa16(a_dst0 + (uint32_t)(s_ * AS_STAGE) * 4, \
              reinterpret_cast<const uint4*>(Asrc_) + aq); \
        const uint4* Bp_ = reinterpret_cast<const uint4*>(g_Wzr + (size_t)(c) * 4096); \
        _Pragma("unroll") \
        for (int t_ = 0; t_ < 4; t_++) { \
            int i_ = tid + t_ * 256; \
            cpa16(bs_b + (uint32_t)(s_ * BS_STAGE + (i_ >> 6) * BSZ_STR + (i_ & 63) * 4) * 4, \
                  Bp_ + i_); \
        } \
        CP_COMMIT(); \
    } while (0)

        STAGE1(0);
        STAGE1(1);

#pragma unroll
        for (int chunk = 0; chunk < 8; chunk++) {
            if (chunk < 7) CP_WAIT(1); else CP_WAIT(0);
            __syncthreads();
            if (chunk <= 5) STAGE1(chunk + 2);

            const unsigned* Asp = As + (chunk % 3) * AS_STAGE;
            const unsigned* Bsp = Bs + (chunk % 3) * BS_STAGE;
#pragma unroll
            for (int ks = 0; ks < 2; ks++) {
                int kb = ks * 8;
                unsigned a[2][4];
#pragma unroll
                for (int mt = 0; mt < 2; mt++) {
                    int rb = wm * 32 + mt * 16 + gid;
                    a[mt][0] = Asp[rb * AS_STR + kb + tig];
                    a[mt][1] = Asp[(rb + 8) * AS_STR + kb + tig];
                    a[mt][2] = Asp[rb * AS_STR + kb + tig + 4];
                    a[mt][3] = Asp[(rb + 8) * AS_STR + kb + tig + 4];
                }
#pragma unroll
                for (int nt = 0; nt < 8; nt++) {
                    unsigned b[2];
                    int cb = wn * 64 + nt * 8 + gid;
                    b[0] = Bsp[(kb + tig) * BSZ_STR + cb];
                    b[1] = Bsp[(kb + tig + 4) * BSZ_STR + cb];
                    mma_f16(acc[0][nt], a[0], b);
                    mma_f16(acc[1][nt], a[1], b);
                }
            }
        }
#undef STAGE1
        __syncthreads();

        // epilogue1
#pragma unroll
        for (int mt = 0; mt < 2; mt++) {
#pragma unroll
            for (int nt = 0; nt < 8; nt++) {
                int col = wn * 64 + nt * 8 + 2 * tig;
                int lr1 = wm * 32 + mt * 16 + gid;
                int lr2 = lr1 + 8;
                float b0 = g_bias_zr[col], b1 = g_bias_zr[col + 1];
                if (wn < 2) {
                    int n = col;
                    *reinterpret_cast<__half2*>(z_h + lr1 * ZSH + n) =
                        __floats2half2_rn(sigmoid_fast(acc[mt][nt][0] + b0),
                                          sigmoid_fast(acc[mt][nt][1] + b1));
                    *reinterpret_cast<__half2*>(z_h + lr2 * ZSH + n) =
                        __floats2half2_rn(sigmoid_fast(acc[mt][nt][2] + b0),
                                          sigmoid_fast(acc[mt][nt][3] + b1));
                } else {
                    int n = col - 128;
                    float2 h1 = __half22float2(__ldg(reinterpret_cast<const __half2*>(
                        g_hh + (size_t)(row0 + lr1) * FF + n)));
                    float2 h2 = __half22float2(__ldg(reinterpret_cast<const __half2*>(
                        g_hh + (size_t)(row0 + lr2) * FF + n)));
                    *reinterpret_cast<__half2*>(hr_h + lr1 * HRH + n) =
                        __floats2half2_rn(sigmoid_fast(acc[mt][nt][0] + b0) * h1.x,
                                          sigmoid_fast(acc[mt][nt][1] + b1) * h1.y);
                    *reinterpret_cast<__half2*>(hr_h + lr2 * HRH + n) =
                        __floats2half2_rn(sigmoid_fast(acc[mt][nt][2] + b0) * h2.x,
                                          sigmoid_fast(acc[mt][nt][3] + b1) * h2.y);
                }
            }
        }
    }
    __syncthreads();

    // ---------------- GEMM2: N=128, A = [ax | hr_h] ----------------
    float acc[2][4][4];
#pragma unroll
    for (int mt = 0; mt < 2; mt++)
#pragma unroll
        for (int nt = 0; nt < 4; nt++)
#pragma unroll
            for (int q = 0; q < 4; q++) acc[mt][nt][q] = 0.f;

#define STAGE2(c) do { \
        int s_ = (c) % 3; \
        if ((c) < 4) { \
            const __half* Asrc_ = axh + (size_t)(row0 + ar) * FF + (c) * KC; \
            cpa16(a_dst0 + (uint32_t)(s_ * AS_STAGE) * 4, \
                  reinterpret_cast<const uint4*>(Asrc_) + aq); \
        } \
        const uint4* Bp_ = reinterpret_cast<const uint4*>(g_Whc + (size_t)(c) * 2048); \
        _Pragma("unroll") \
        for (int t_ = 0; t_ < 2; t_++) { \
            int i_ = tid + t_ * 256; \
            cpa16(bs_b + (uint32_t)(s_ * BS_STAGE + (i_ >> 5) * BSC_STR + (i_ & 31) * 4) * 4, \
                  Bp_ + i_); \
        } \
        CP_COMMIT(); \
    } while (0)

    STAGE2(0);
    STAGE2(1);

#pragma unroll
    for (int chunk = 0; chunk < 8; chunk++) {
        if (chunk < 7) CP_WAIT(1); else CP_WAIT(0);
        __syncthreads();
        if (chunk <= 5) STAGE2(chunk + 2);

        const unsigned* Asp = As + (chunk % 3) * AS_STAGE;
        const unsigned* Bsp = Bs + (chunk % 3) * BS_STAGE;
#pragma unroll
        for (int ks = 0; ks < 2; ks++) {
            int kb = ks * 8;
            unsigned a[2][4];
#pragma unroll
            for (int mt = 0; mt < 2; mt++) {
                int rb = wm * 32 + mt * 16 + gid;
                if (chunk < 4) {
                    a[mt][0] = Asp[rb * AS_STR + kb + tig];
                    a[mt][1] = Asp[(rb + 8) * AS_STR + kb + tig];
                    a[mt][2] = Asp[rb * AS_STR + kb + tig + 4];
                    a[mt][3] = Asp[(rb + 8) * AS_STR + kb + tig + 4];
                } else {
                    int kf = (chunk - 4) * KC + ks * 16 + 2 * tig;
                    a[mt][0] = *reinterpret_cast<const unsigned*>(hr_h + rb * HRH + kf);
                    a[mt][1] = *reinterpret_cast<const unsigned*>(hr_h + (rb + 8) * HRH + kf);
                    a[mt][2] = *reinterpret_cast<const unsigned*>(hr_h + rb * HRH + kf + 8);
                    a[mt][3] = *reinterpret_cast<const unsigned*>(hr_h + (rb + 8) * HRH + kf + 8);
                }
            }
#pragma unroll
            for (int nt = 0; nt < 4; nt++) {
                unsigned b[2];
                int cb = wn * 32 + nt * 8 + gid;
                b[0] = Bsp[(kb + tig) * BSC_STR + cb];
                b[1] = Bsp[(kb + tig + 4) * BSC_STR + cb];
                mma_f16(acc[0][nt], a[0], b);
                mma_f16(acc[1][nt], a[1], b);
            }
        }
    }
#undef STAGE2

    // epilogue2
#pragma unroll
    for (int mt = 0; mt < 2; mt++) {
#pragma unroll
        for (int nt = 0; nt < 4; nt++) {
            int n = wn * 32 + nt * 8 + 2 * tig;
            float b0 = g_bias_c[n], b1 = g_bias_c[n + 1];
#pragma unroll
            for (int half = 0; half < 2; half++) {
                int lr = wm * 32 + mt * 16 + gid + half * 8;
                int row = row0 + lr;
                float c0 = tanh_fast(acc[mt][nt][half * 2]     + b0);
                float c1 = tanh_fast(acc[mt][nt][half * 2 + 1] + b1);
                float2 zv = __half22float2(
                    *reinterpret_cast<const __half2*>(z_h + lr * ZSH + n));
                float2 hr = __half22float2(
                    *reinterpret_cast<const __half2*>(hr_h + lr * HRH + n));
                float2 hn = make_float2((1.f - zv.x) * hr.x, (1.f - zv.y) * hr.y);
                size_t idx = (size_t)row * FF + n;
                *reinterpret_cast<__half2*>(g_hh + idx) = __floats2half2_rn(hn.x, hn.y);
                float2 ov = *reinterpret_cast<float2*>(g_out + idx);
                ov.x += hn.x + zv.x * c0;
                ov.y += hn.y + zv.y * c1;
                *reinterpret_cast<float2*>(g_out + idx) = ov;
            }
        }
    }
}

// ---------------- pooling + classifier ----------------
__global__ void k_pool(const float* __restrict__ Wlin, const float* __restrict__ blin,
                       float* __restrict__ y) {
    int g = blockIdx.x;
    int f = threadIdx.x;
    const float* base = g_out + (size_t)g * NPG * FF + f;
    float s = 0.f;
#pragma unroll 4
    for (int n = 0; n < NPG; n++) s += base[(size_t)n * FF];
    s *= (1.0f / (float)NPG);
    float p0 = s * __ldg(Wlin + 2 * f);
    float p1 = s * __ldg(Wlin + 2 * f + 1);
#pragma unroll
    for (int off = 16; off > 0; off >>= 1) {
        p0 += __shfl_down_sync(0xffffffffu, p0, off);
        p1 += __shfl_down_sync(0xffffffffu, p1, off);
    }
    __shared__ float r0s[4], r1s[4];
    int w = f >> 5, lane = f & 31;
    if (lane == 0) { r0s[w] = p0; r1s[w] = p1; }
    __syncthreads();
    if (f == 0) {
        y[2 * g]     = r0s[0] + r0s[1] + r0s[2] + r0s[3] + __ldg(blin);
        y[2 * g + 1] = r1s[0] + r1s[1] + r1s[2] + r1s[3] + __ldg(blin + 1);
    }
}

// ---------------- launch: sparse pipeline on a second stream, overlapped with GRU ----------------
extern "C" void kernel_launch(void* const* d_in, const int* in_sizes, int n_in,
                              void* d_out, int out_size) {
    const float* xs = nullptr;
    const float* eas = nullptr;
    const int*   eis = nullptr;
    const float* Wg[6] = {nullptr, nullptr, nullptr, nullptr, nullptr, nullptr};
    const float* bg[6] = {nullptr, nullptr, nullptr, nullptr, nullptr, nullptr};
    const float* Wlin = nullptr;
    const float* blin = nullptr;
    int wi = 0, bi = 0;
    for (int i = 0; i < n_in; i++) {
        long sz = in_sizes[i];
        void* p = d_in[i];
        if (sz == (long)TT * NN * FF)      xs  = (const float*)p;
        else if (sz == (long)TT * EE)      eas = (const float*)p;
        else if (sz == (long)2 * TT * EE)  eis = (const int*)p;
        else if (sz == (long)NN)           { /* batch: contiguous by construction */ }
        else if (sz == (long)FF * FF && wi < 6) Wg[wi++] = (const float*)p;
        else if (sz == (long)FF && bi < 6)      bg[bi++] = (const float*)p;
        else if (sz == (long)FF * CC)      Wlin = (const float*)p;
        else if (sz == (long)CC)           blin = (const float*)p;
    }
    float* y = (float*)d_out;

    const int SMEM_GRU = AS_TOT * 4 + BS_TOT * 4 + BM * HRH * 2 + BM * ZSH * 2;
    cudaFuncSetAttribute(k_gru, cudaFuncAttributeMaxDynamicSharedMemorySize, SMEM_GRU);

    // second stream + events (host objects; no device memory). Fresh per call.
    cudaStream_t s2;
    cudaStreamCreateWithFlags(&s2, cudaStreamNonBlocking);
    cudaEvent_t e0, eAgg[TT];
    cudaEventCreateWithFlags(&e0, cudaEventDisableTiming);
    for (int t = 0; t < TT; t++) cudaEventCreateWithFlags(&eAgg[t], cudaEventDisableTiming);

    // fork: s2 starts as soon as prior default-stream work (input readiness) is ordered
    cudaEventRecord(e0, 0);
    cudaStreamWaitEvent(s2, e0, 0);

    // default stream: init + weight pack (needed by k_gru)
    k_init_hout<<<(NN * FF / 4 + 255) / 256, 256>>>();
    k_pack<<<(32768 + 16384 + 384 + 255) / 256, 256>>>(
        Wg[0], bg[0], Wg[1], bg[1], Wg[2], bg[2],
        Wg[3], bg[3], Wg[4], bg[4], Wg[5], bg[5]);

    // s2: per-step sparse pipelines (h-independent)
    for (int t = 0; t < TT; t++) {
        k_h16 <<<(NN * FF / 8 + 255) / 256, 256, 0, s2>>>(t, xs);
        k_prep<<<(NN + 255) / 256, 256, 0, s2>>>(t);
        k_cnt <<<(EE + 255) / 256, 256, 0, s2>>>(t, eis);
        k_scan1<<<NBLK, 256, 0, s2>>>(t);
        k_scan2<<<1, 512, 0, s2>>>(t);
        k_scan3<<<NBLK, 256, 0, s2>>>(t);
        k_fill<<<(EE + 255) / 256, 256, 0, s2>>>(t, eas, eis);
        k_deg <<<(NN + 255) / 256, 256, 0, s2>>>(t);
        k_norm<<<(EE + 255) / 256, 256, 0, s2>>>(t);
        k_agg <<<(NN * 32 + 255) / 256, 256, 0, s2>>>(t);
        cudaEventRecord(eAgg[t], s2);
    }

    // default stream: sequential GRU steps; step t joins with agg(t)
    for (int t = 0; t < TT; t++) {
        cudaStreamWaitEvent(0, eAgg[t], 0);
        k_gru<<<NN / BM, 256, SMEM_GRU>>>(t);
    }
    k_pool<<<BB, 128>>>(Wlin, blin, y);
}

// round 15
// speedup vs baseline: 1.0350x; 1.0350x over previous
#include <cuda_runtime.h>
#include <cuda_fp16.h>
#include <cstdint>

#define NN 113664
#define FF 128
#define EE 909312
#define TT 4
#define BB 1024
#define CC 2
#define NPG 111        // nodes per graph = NN/BB
#define NBLK 444       // NN / 256

// GEMM tiling (fp16 mma.m16n8k16), BM=64 rows/CTA, 256 threads, 2 CTAs/SM
#define BM 64
#define KC 32          // K floats per chunk (16 half2)
#define AS_STR 20      // A row stride in uints -> conflict-free frags
#define BSZ_STR 264    // B k2-row stride GEMM1 (n=256)
#define BSC_STR 136    // B k2-row stride GEMM2 (n=128)
#define ZSH 136        // z fp16 smem stride (halves)
#define AS_STAGE (BM * AS_STR)       // 1280 uints per A chunk
#define BS_STAGE (16 * BSZ_STR)      // 4224 uints per B slot
#define ARES_TOT (8 * AS_STAGE)      // 10240 uints: all 8 A chunks resident
#define BS_TOT (3 * BS_STAGE)        // 12672 uints: 3-slot B ring

// ---------------- device scratch (static: no runtime allocation) ----------------
__device__ float g_dinv[TT * NN];
__device__ int   g_cnt [TT * NN];
__device__ int   g_rowptr[TT * (NN + 1)];
__device__ int   g_cursor[TT * NN];
__device__ int   g_bsum[TT * NBLK];
__device__ int   g_boff[TT * (NBLK + 1)];
__device__ int2  g_cv[TT * EE];          // packed (col, val-bits) per edge
__device__ __half g_xh [TT * NN * FF];   // fp16 copy of xs
__device__ __half g_axh[TT * NN * FF];   // fp16 aggregated features
__device__ __half g_hh [NN * FF];        // fp16 hidden state
__device__ float g_out[NN * FF];
__device__ unsigned g_Wzr[128 * 256];   // half2 packed [k2][n]: n<128:z n>=128:r
__device__ unsigned g_Whc[128 * 128];   // half2 packed [k2][n]
__device__ float g_bias_zr[256];
__device__ float g_bias_c[128];

// ---------------- math helpers ----------------
__device__ __forceinline__ float tanh_fast(float x) {
    float y;
    asm("tanh.approx.f32 %0, %1;" : "=f"(y) : "f"(x));
    return y;
}
__device__ __forceinline__ float sigmoid_fast(float x) {
    return 0.5f * tanh_fast(0.5f * x) + 0.5f;
}
__device__ __forceinline__ unsigned pkh2(float a, float b) {
    __half2 h = __float22half2_rn(make_float2(a, b));
    return *reinterpret_cast<unsigned*>(&h);
}
__device__ __forceinline__ void mma_f16(float d[4], const unsigned a[4], const unsigned b[2]) {
    asm volatile(
        "mma.sync.aligned.m16n8k16.row.col.f32.f16.f16.f32 "
        "{%0,%1,%2,%3}, {%4,%5,%6,%7}, {%8,%9}, {%0,%1,%2,%3};"
        : "+f"(d[0]), "+f"(d[1]), "+f"(d[2]), "+f"(d[3])
        : "r"(a[0]), "r"(a[1]), "r"(a[2]), "r"(a[3]), "r"(b[0]), "r"(b[1]));
}
__device__ __forceinline__ uint32_t smem_u32(const void* p) {
    uint32_t a;
    asm("{ .reg .u64 t; cvta.to.shared.u64 t, %1; cvt.u32.u64 %0, t; }" : "=r"(a) : "l"(p));
    return a;
}
__device__ __forceinline__ void cpa16(uint32_t dst, const void* src) {
    asm volatile("cp.async.cg.shared.global [%0], [%1], 16;" :: "r"(dst), "l"(src));
}
#define CP_COMMIT() asm volatile("cp.async.commit_group;" ::: "memory")
#define CP_WAIT(n)  asm volatile("cp.async.wait_group %0;" :: "n"(n) : "memory")

// ---------------- init: hh = eye(N,F) fp16, out = 0 ----------------
__global__ void k_init_hout() {
    int idx = blockIdx.x * blockDim.x + threadIdx.x;
    if (idx >= NN * FF / 4) return;
    reinterpret_cast<float4*>(g_out)[idx] = make_float4(0.f, 0.f, 0.f, 0.f);
    if (idx < NN * FF / 8) {
        int base = idx * 8;
        int row = base >> 7;
        int c0 = base & 127;
        __half h8[8];
#pragma unroll
        for (int u = 0; u < 8; u++) h8[u] = __float2half(0.f);
        if (row < FF && row >= c0 && row < c0 + 8) h8[row - c0] = __float2half(1.f);
        reinterpret_cast<uint4*>(g_hh)[idx] = *reinterpret_cast<uint4*>(h8);
    }
}

// ---------------- xs -> fp16 (all steps) ----------------
__global__ void k_h16(const float* __restrict__ xs) {
    size_t idx = (size_t)blockIdx.x * blockDim.x + threadIdx.x;
    if (idx >= (size_t)TT * NN * FF / 8) return;
    const float4* src = reinterpret_cast<const float4*>(xs) + idx * 2;
    float4 v0 = __ldg(src), v1 = __ldg(src + 1);
    uint4 o = make_uint4(pkh2(v0.x, v0.y), pkh2(v0.z, v0.w),
                         pkh2(v1.x, v1.y), pkh2(v1.z, v1.w));
    reinterpret_cast<uint4*>(g_xh)[idx] = o;
}

// ---------------- weight packing: half2 [k2][n] + fused biases ----------------
__global__ void k_pack(const float* __restrict__ Wzi, const float* __restrict__ bzi,
                       const float* __restrict__ Wzh, const float* __restrict__ bzh,
                       const float* __restrict__ Wri, const float* __restrict__ bri,
                       const float* __restrict__ Wrh, const float* __restrict__ brh,
                       const float* __restrict__ Whi, const float* __restrict__ bhi,
                       const float* __restrict__ Whh, const float* __restrict__ bhh) {
    int i = blockIdx.x * blockDim.x + threadIdx.x;
    if (i < 32768) {                       // g_Wzr: [k2=0..127][n=0..255]
        int k2 = i >> 8, n = i & 255;
        int k = 2 * k2;
        float v0, v1;
        if (k < 128) {
            v0 = (n < 128) ? Wzi[k * 128 + n]       : Wri[k * 128 + (n - 128)];
            v1 = (n < 128) ? Wzi[(k + 1) * 128 + n] : Wri[(k + 1) * 128 + (n - 128)];
        } else {
            int kk = k - 128;
            v0 = (n < 128) ? Wzh[kk * 128 + n]       : Wrh[kk * 128 + (n - 128)];
            v1 = (n < 128) ? Wzh[(kk + 1) * 128 + n] : Wrh[(kk + 1) * 128 + (n - 128)];
        }
        g_Wzr[i] = pkh2(v0, v1);
    } else if (i < 32768 + 16384) {        // g_Whc: [k2=0..127][n=0..127]
        int j = i - 32768;
        int k2 = j >> 7, n = j & 127;
        int k = 2 * k2;
        float v0, v1;
        if (k < 128) { v0 = Whi[k * 128 + n]; v1 = Whi[(k + 1) * 128 + n]; }
        else { int kk = k - 128; v0 = Whh[kk * 128 + n]; v1 = Whh[(kk + 1) * 128 + n]; }
        g_Whc[j] = pkh2(v0, v1);
    } else if (i < 32768 + 16384 + 256) {
        int n = i - (32768 + 16384);
        g_bias_zr[n] = (n < 128) ? (bzi[n] + bzh[n]) : (bri[n - 128] + brh[n - 128]);
    } else if (i < 32768 + 16384 + 384) {
        int n = i - (32768 + 16384 + 256);
        g_bias_c[n] = bhi[n] + bhh[n];
    }
}

// ---------------- batched per-step CSR build ----------------
__global__ void k_prep4() {
    int i = blockIdx.x * blockDim.x + threadIdx.x;
    if (i < TT * NN) g_cnt[i] = 0;
}

__global__ void k_cnt4(const int* __restrict__ eis) {
    int e = blockIdx.x * blockDim.x + threadIdx.x;
    int t = blockIdx.y;
    if (e >= EE) return;
    int d = eis[(size_t)t * 2 * EE + EE + e];
    atomicAdd(&g_cnt[t * NN + d], 1);
}

__global__ void k_scan1() {
    __shared__ int sh[256];
    int tid = threadIdx.x;
    int t = blockIdx.y;
    sh[tid] = g_cnt[t * NN + blockIdx.x * 256 + tid];
    __syncthreads();
#pragma unroll
    for (int off = 128; off > 0; off >>= 1) {
        if (tid < off) sh[tid] += sh[tid + off];
        __syncthreads();
    }
    if (tid == 0) g_bsum[t * NBLK + blockIdx.x] = sh[0];
}

__global__ void k_scan2() {
    __shared__ int sh[512];
    int tid = threadIdx.x;
    int t = blockIdx.x;
    int v = (tid < NBLK) ? g_bsum[t * NBLK + tid] : 0;
    sh[tid] = v;
    __syncthreads();
#pragma unroll
    for (int off = 1; off < 512; off <<= 1) {
        int u = (tid >= off) ? sh[tid - off] : 0;
        __syncthreads();
        sh[tid] += u;
        __syncthreads();
    }
    if (tid < NBLK) g_boff[t * (NBLK + 1) + tid] = sh[tid] - v;
    if (tid == NBLK - 1) g_boff[t * (NBLK + 1) + NBLK] = sh[tid];
}

__global__ void k_scan3() {
    __shared__ int sh[256];
    int tid = threadIdx.x;
    int t = blockIdx.y;
    int i = blockIdx.x * 256 + tid;
    int c = g_cnt[t * NN + i];
    sh[tid] = c;
    __syncthreads();
#pragma unroll
    for (int off = 1; off < 256; off <<= 1) {
        int u = (tid >= off) ? sh[tid - off] : 0;
        __syncthreads();
        sh[tid] += u;
        __syncthreads();
    }
    int excl = sh[tid] - c + g_boff[t * (NBLK + 1) + blockIdx.x];
    g_rowptr[t * (NN + 1) + i] = excl;
    g_cursor[t * NN + i] = excl;
    if (i == NN - 1) g_rowptr[t * (NN + 1) + NN] = excl + c;
}

__global__ void k_fill4(const float* __restrict__ eas, const int* __restrict__ eis) {
    int e = blockIdx.x * blockDim.x + threadIdx.x;
    int t = blockIdx.y;
    if (e >= EE) return;
    int s = eis[(size_t)t * 2 * EE + e];
    int d = eis[(size_t)t * 2 * EE + EE + e];
    int pos = atomicAdd(&g_cursor[t * NN + d], 1);
    g_cv[(size_t)t * EE + pos] = make_int2(s, __float_as_int(eas[(size_t)t * EE + e]));
}

__global__ void k_deg4() {
    int i = blockIdx.x * blockDim.x + threadIdx.x;
    if (i >= TT * NN) return;
    int t = i / NN;
    int nidx = i - t * NN;
    int beg = g_rowptr[t * (NN + 1) + nidx], end = g_rowptr[t * (NN + 1) + nidx + 1];
    const int2* cv = g_cv + (size_t)t * EE;
    float s = 1.0f;
    for (int j = beg; j < end; j++) s += __int_as_float(cv[j].y);
    g_dinv[i] = rsqrtf(s);
}

// pre-normalize: val[e] *= dinv[col[e]]
__global__ void k_norm4() {
    size_t e = (size_t)blockIdx.x * blockDim.x + threadIdx.x;
    if (e >= (size_t)TT * EE) return;
    int t = (int)(e / EE);
    int2 cv = g_cv[e];
    cv.y = __float_as_int(__int_as_float(cv.y) * g_dinv[t * NN + cv.x]);
    g_cv[e] = cv;
}

// ---------------- sparse aggregate (fp16 gather, lane-parallel edges, 4x MLP) ----------------
__global__ void k_agg4() {
    int gw = (blockIdx.x * blockDim.x + threadIdx.x) >> 5;
    int t = blockIdx.y;
    if (gw >= NN) return;
    int lane = threadIdx.x & 31;

    const __half* x = g_xh + (size_t)t * NN * FF;
    float dinv_d = g_dinv[t * NN + gw];
    float self = dinv_d * dinv_d;

    uint2 raw = __ldg(reinterpret_cast<const uint2*>(x + (size_t)gw * FF) + lane);
    float2 xv0 = __half22float2(*reinterpret_cast<const __half2*>(&raw.x));
    float2 xv1 = __half22float2(*reinterpret_cast<const __half2*>(&raw.y));

    float4 a = make_float4(0.f, 0.f, 0.f, 0.f);
    int beg = g_rowptr[t * (NN + 1) + gw], end = g_rowptr[t * (NN + 1) + gw + 1];
    const int2* cvp = g_cv + (size_t)t * EE;

    for (int base = beg; base < end; base += 32) {
        int j = base + lane;
        int2 cv = (j < end) ? __ldg(cvp + j) : make_int2(0, 0);
        int cnt = min(32, end - base);
        int k = 0;
        // 4-wide: 4 independent gathers in flight
        for (; k + 4 <= cnt; k += 4) {
            int s0 = __shfl_sync(0xffffffffu, cv.x, k);
            int s1 = __shfl_sync(0xffffffffu, cv.x, k + 1);
            int s2 = __shfl_sync(0xffffffffu, cv.x, k + 2);
            int s3 = __shfl_sync(0xffffffffu, cv.x, k + 3);
            float v0 = __int_as_float(__shfl_sync(0xffffffffu, cv.y, k));
            float v1 = __int_as_float(__shfl_sync(0xffffffffu, cv.y, k + 1));
            float v2 = __int_as_float(__shfl_sync(0xffffffffu, cv.y, k + 2));
            float v3 = __int_as_float(__shfl_sync(0xffffffffu, cv.y, k + 3));
            uint2 r0 = __ldg(reinterpret_cast<const uint2*>(x + (size_t)s0 * FF) + lane);
            uint2 r1 = __ldg(reinterpret_cast<const uint2*>(x + (size_t)s1 * FF) + lane);
            uint2 r2 = __ldg(reinterpret_cast<const uint2*>(x + (size_t)s2 * FF) + lane);
            uint2 r3 = __ldg(reinterpret_cast<const uint2*>(x + (size_t)s3 * FF) + lane);
            float2 f;
            f = __half22float2(*reinterpret_cast<const __half2*>(&r0.x)); a.x += v0 * f.x; a.y += v0 * f.y;
            f = __half22float2(*reinterpret_cast<const __half2*>(&r0.y)); a.z += v0 * f.x; a.w += v0 * f.y;
            f = __half22float2(*reinterpret_cast<const __half2*>(&r1.x)); a.x += v1 * f.x; a.y += v1 * f.y;
            f = __half22float2(*reinterpret_cast<const __half2*>(&r1.y)); a.z += v1 * f.x; a.w += v1 * f.y;
            f = __half22float2(*reinterpret_cast<const __half2*>(&r2.x)); a.x += v2 * f.x; a.y += v2 * f.y;
            f = __half22float2(*reinterpret_cast<const __half2*>(&r2.y)); a.z += v2 * f.x; a.w += v2 * f.y;
            f = __half22float2(*reinterpret_cast<const __half2*>(&r3.x)); a.x += v3 * f.x; a.y += v3 * f.y;
            f = __half22float2(*reinterpret_cast<const __half2*>(&r3.y)); a.z += v3 * f.x; a.w += v3 * f.y;
        }
        for (; k < cnt; k++) {
            int   s = __shfl_sync(0xffffffffu, cv.x, k);
            float v = __int_as_float(__shfl_sync(0xffffffffu, cv.y, k));
            uint2 rw = __ldg(reinterpret_cast<const uint2*>(x + (size_t)s * FF) + lane);
            float2 f0 = __half22float2(*reinterpret_cast<const __half2*>(&rw.x));
            float2 f1 = __half22float2(*reinterpret_cast<const __half2*>(&rw.y));
            a.x += v * f0.x; a.y += v * f0.y; a.z += v * f1.x; a.w += v * f1.y;
        }
    }
    a.x = dinv_d * a.x + self * xv0.x;
    a.y = dinv_d * a.y + self * xv0.y;
    a.z = dinv_d * a.z + self * xv1.x;
    a.w = dinv_d * a.w + self * xv1.y;
    uint2 w;
    w.x = pkh2(a.x, a.y);
    w.y = pkh2(a.z, a.w);
    reinterpret_cast<uint2*>(g_axh + (size_t)t * NN * FF + (size_t)gw * FF)[lane] = w;
}

// ================= Fused GRU step: resident-A + 3-slot B ring (cp.async) =================
// BM=64, 256 thr, 8 warps as 2x4; 2 CTAs/SM. All 8 A chunks staged once (ARes);
// h region of ARes is overwritten with hr by epilogue1 and reused by GEMM2.
__global__ void __launch_bounds__(256, 2) k_gru(int step) {
    extern __shared__ unsigned sm[];
    unsigned* Ares = sm;                                  // 8 x AS_STAGE
    unsigned* Bs = sm + ARES_TOT;                         // 3 x BS_STAGE
    __half* z_h = reinterpret_cast<__half*>(sm + ARES_TOT + BS_TOT);  // [64][ZSH]

    const uint32_t ares_b = smem_u32(Ares);
    const uint32_t bs_b = smem_u32(Bs);

    const __half* axh = g_axh + (size_t)step * NN * FF;
    const int tid = threadIdx.x;
    const int w = tid >> 5, lane = tid & 31;
    const int wm = w & 1, wn = w >> 1;
    const int gid = lane >> 2, tig = lane & 3;
    const int row0 = blockIdx.x * BM;
    const int ar = tid >> 2, aq = tid & 3;

    const uint32_t a_dst0 = ares_b + (uint32_t)(ar * AS_STR + aq * 4) * 4;

    // ---------------- prologue: group0 = all 8 A chunks + B0; group1 = B1 ----------------
    {
#pragma unroll
        for (int c = 0; c < 8; c++) {
            const __half* Asrc = ((c < 4) ? axh : g_hh)
                               + (size_t)(row0 + ar) * FF + (c & 3) * KC;
            cpa16(a_dst0 + (uint32_t)(c * AS_STAGE) * 4,
                  reinterpret_cast<const uint4*>(Asrc) + aq);
        }
        const uint4* Bp = reinterpret_cast<const uint4*>(g_Wzr);
#pragma unroll
        for (int t_ = 0; t_ < 4; t_++) {
            int i_ = tid + t_ * 256;
            cpa16(bs_b + (uint32_t)((i_ >> 6) * BSZ_STR + (i_ & 63) * 4) * 4, Bp + i_);
        }
        CP_COMMIT();
        const uint4* Bp1 = reinterpret_cast<const uint4*>(g_Wzr + 4096);
#pragma unroll
        for (int t_ = 0; t_ < 4; t_++) {
            int i_ = tid + t_ * 256;
            cpa16(bs_b + (uint32_t)(BS_STAGE + (i_ >> 6) * BSZ_STR + (i_ & 63) * 4) * 4, Bp1 + i_);
        }
        CP_COMMIT();
    }

    // ---------------- GEMM1: N=256 ----------------
    float acc1[2][8][4];
#pragma unroll
    for (int mt = 0; mt < 2; mt++)
#pragma unroll
        for (int nt = 0; nt < 8; nt++)
#pragma unroll
            for (int q = 0; q < 4; q++) acc1[mt][nt][q] = 0.f;

#pragma unroll
    for (int chunk = 0; chunk < 8; chunk++) {
        if (chunk < 7) CP_WAIT(1); else CP_WAIT(0);
        __syncthreads();
        if (chunk <= 5) {
            int c2 = chunk + 2, s_ = c2 % 3;
            const uint4* Bp = reinterpret_cast<const uint4*>(g_Wzr + (size_t)c2 * 4096);
#pragma unroll
            for (int t_ = 0; t_ < 4; t_++) {
                int i_ = tid + t_ * 256;
                cpa16(bs_b + (uint32_t)(s_ * BS_STAGE + (i_ >> 6) * BSZ_STR + (i_ & 63) * 4) * 4,
                      Bp + i_);
            }
            CP_COMMIT();
        }
        const unsigned* Asp = Ares + chunk * AS_STAGE;
        const unsigned* Bsp = Bs + (chunk % 3) * BS_STAGE;
#pragma unroll
        for (int ks = 0; ks < 2; ks++) {
            int kb = ks * 8;
            unsigned a[2][4];
#pragma unroll
            for (int mt = 0; mt < 2; mt++) {
                int rb = wm * 32 + mt * 16 + gid;
                a[mt][0] = Asp[rb * AS_STR + kb + tig];
                a[mt][1] = Asp[(rb + 8) * AS_STR + kb + tig];
                a[mt][2] = Asp[rb * AS_STR + kb + tig + 4];
                a[mt][3] = Asp[(rb + 8) * AS_STR + kb + tig + 4];
            }
#pragma unroll
            for (int nt = 0; nt < 8; nt++) {
                unsigned b[2];
                int cb = wn * 64 + nt * 8 + gid;
                b[0] = Bsp[(kb + tig) * BSZ_STR + cb];
                b[1] = Bsp[(kb + tig + 4) * BSZ_STR + cb];
                mma_f16(acc1[0][nt], a[0], b);
                mma_f16(acc1[1][nt], a[1], b);
            }
        }
    }
    __syncthreads();   // GEMM1 done: ring free, h region safe to overwrite

    // prefetch GEMM2 B0,B1 (overlaps epilogue1)
    {
        const uint4* Bp = reinterpret_cast<const uint4*>(g_Whc);
#pragma unroll
        for (int t_ = 0; t_ < 2; t_++) {
            int i_ = tid + t_ * 256;
            cpa16(bs_b + (uint32_t)((i_ >> 5) * BSC_STR + (i_ & 31) * 4) * 4, Bp + i_);
        }
        CP_COMMIT();
        const uint4* Bp1 = reinterpret_cast<const uint4*>(g_Whc + 2048);
#pragma unroll
        for (int t_ = 0; t_ < 2; t_++) {
            int i_ = tid + t_ * 256;
            cpa16(bs_b + (uint32_t)(BS_STAGE + (i_ >> 5) * BSC_STR + (i_ & 31) * 4) * 4, Bp1 + i_);
        }
        CP_COMMIT();
    }

    // epilogue1: wn 0,1 -> z (fp16); wn 2,3 -> hr = sig(.)*h, written over h in ARes
#pragma unroll
    for (int mt = 0; mt < 2; mt++) {
#pragma unroll
        for (int nt = 0; nt < 8; nt++) {
            int col = wn * 64 + nt * 8 + 2 * tig;
            int lr1 = wm * 32 + mt * 16 + gid;
            int lr2 = lr1 + 8;
            float b0 = g_bias_zr[col], b1 = g_bias_zr[col + 1];
            if (wn < 2) {
                int n = col;
                *reinterpret_cast<__half2*>(z_h + lr1 * ZSH + n) =
                    __floats2half2_rn(sigmoid_fast(acc1[mt][nt][0] + b0),
                                      sigmoid_fast(acc1[mt][nt][1] + b1));
                *reinterpret_cast<__half2*>(z_h + lr2 * ZSH + n) =
                    __floats2half2_rn(sigmoid_fast(acc1[mt][nt][2] + b0),
                                      sigmoid_fast(acc1[mt][nt][3] + b1));
            } else {
                int n = col - 128;
                int uoff = (4 + (n >> 5)) * AS_STAGE + ((n & 31) >> 1);
                __half2* p1 = reinterpret_cast<__half2*>(&Ares[uoff + lr1 * AS_STR]);
                __half2* p2 = reinterpret_cast<__half2*>(&Ares[uoff + lr2 * AS_STR]);
                float2 h1 = __half22float2(*p1);
                float2 h2 = __half22float2(*p2);
                *p1 = __floats2half2_rn(sigmoid_fast(acc1[mt][nt][0] + b0) * h1.x,
                                        sigmoid_fast(acc1[mt][nt][1] + b1) * h1.y);
                *p2 = __floats2half2_rn(sigmoid_fast(acc1[mt][nt][2] + b0) * h2.x,
                                        sigmoid_fast(acc1[mt][nt][3] + b1) * h2.y);
            }
        }
    }

    // ---------------- GEMM2: N=128, A = ARes (ax chunks 0-3, hr chunks 4-7) ----------------
    float acc[2][4][4];
#pragma unroll
    for (int mt = 0; mt < 2; mt++)
#pragma unroll
        for (int nt = 0; nt < 4; nt++)
#pragma unroll
            for (int q = 0; q < 4; q++) acc[mt][nt][q] = 0.f;

#pragma unroll
    for (int chunk = 0; chunk < 8; chunk++) {
        if (chunk < 7) CP_WAIT(1); else CP_WAIT(0);
        __syncthreads();   // first iteration also publishes epilogue1's hr/z writes
        if (chunk <= 5) {
            int c2 = chunk + 2, s_ = c2 % 3;
            const uint4* Bp = reinterpret_cast<const uint4*>(g_Whc + (size_t)c2 * 2048);
#pragma unroll
            for (int t_ = 0; t_ < 2; t_++) {
                int i_ = tid + t_ * 256;
                cpa16(bs_b + (uint32_t)(s_ * BS_STAGE + (i_ >> 5) * BSC_STR + (i_ & 31) * 4) * 4,
                      Bp + i_);
            }
            CP_COMMIT();
        }
        const unsigned* Asp = Ares + chunk * AS_STAGE;
        const unsigned* Bsp = Bs + (chunk % 3) * BS_STAGE;
#pragma unroll
        for (int ks = 0; ks < 2; ks++) {
            int kb = ks * 8;
            unsigned a[2][4];
#pragma unroll
            for (int mt = 0; mt < 2; mt++) {
                int rb = wm * 32 + mt * 16 + gid;
                a[mt][0] = Asp[rb * AS_STR + kb + tig];
                a[mt][1] = Asp[(rb + 8) * AS_STR + kb + tig];
                a[mt][2] = Asp[rb * AS_STR + kb + tig + 4];
                a[mt][3] = Asp[(rb + 8) * AS_STR + kb + tig + 4];
            }
#pragma unroll
            for (int nt = 0; nt < 4; nt++) {
                unsigned b[2];
                int cb = wn * 32 + nt * 8 + gid;
                b[0] = Bsp[(kb + tig) * BSC_STR + cb];
                b[1] = Bsp[(kb + tig + 4) * BSC_STR + cb];
                mma_f16(acc[0][nt], a[0], b);
                mma_f16(acc[1][nt], a[1], b);
            }
        }
    }

    // epilogue2: cand = tanh(acc + bias); hn = (1-z)*hr; hh = hn; out += hn + z*cand
#pragma unroll
    for (int mt = 0; mt < 2; mt++) {
#pragma unroll
        for (int nt = 0; nt < 4; nt++) {
            int n = wn * 32 + nt * 8 + 2 * tig;
            float b0 = g_bias_c[n], b1 = g_bias_c[n + 1];
            int uoff = (4 + (n >> 5)) * AS_STAGE + ((n & 31) >> 1);
#pragma unroll
            for (int half = 0; half < 2; half++) {
                int lr = wm * 32 + mt * 16 + gid + half * 8;
                int row = row0 + lr;
                float c0 = tanh_fast(acc[mt][nt][half * 2]     + b0);
                float c1 = tanh_fast(acc[mt][nt][half * 2 + 1] + b1);
                float2 zv = __half22float2(
                    *reinterpret_cast<const __half2*>(z_h + lr * ZSH + n));
                float2 hr = __half22float2(
                    *reinterpret_cast<const __half2*>(&Ares[uoff + lr * AS_STR]));
                float2 hn = make_float2((1.f - zv.x) * hr.x, (1.f - zv.y) * hr.y);
                size_t idx = (size_t)row * FF + n;
                *reinterpret_cast<__half2*>(g_hh + idx) = __floats2half2_rn(hn.x, hn.y);
                float2 ov = *reinterpret_cast<float2*>(g_out + idx);
                ov.x += hn.x + zv.x * c0;
                ov.y += hn.y + zv.y * c1;
                *reinterpret_cast<float2*>(g_out + idx) = ov;
            }
        }
    }
}

// ---------------- pooling + classifier ----------------
__global__ void k_pool(const float* __restrict__ Wlin, const float* __restrict__ blin,
                       float* __restrict__ y) {
    int g = blockIdx.x;
    int f = threadIdx.x;
    const float* base = g_out + (size_t)g * NPG * FF + f;
    float s = 0.f;
#pragma unroll 4
    for (int n = 0; n < NPG; n++) s += base[(size_t)n * FF];
    s *= (1.0f / (float)NPG);
    float p0 = s * __ldg(Wlin + 2 * f);
    float p1 = s * __ldg(Wlin + 2 * f + 1);
#pragma unroll
    for (int off = 16; off > 0; off >>= 1) {
        p0 += __shfl_down_sync(0xffffffffu, p0, off);
        p1 += __shfl_down_sync(0xffffffffu, p1, off);
    }
    __shared__ float r0s[4], r1s[4];
    int w = f >> 5, lane = f & 31;
    if (lane == 0) { r0s[w] = p0; r1s[w] = p1; }
    __syncthreads();
    if (f == 0) {
        y[2 * g]     = r0s[0] + r0s[1] + r0s[2] + r0s[3] + __ldg(blin);
        y[2 * g + 1] = r1s[0] + r1s[1] + r1s[2] + r1s[3] + __ldg(blin + 1);
    }
}

// ---------------- launch (serial, batched sparse) ----------------
extern "C" void kernel_launch(void* const* d_in, const int* in_sizes, int n_in,
                              void* d_out, int out_size) {
    const float* xs = nullptr;
    const float* eas = nullptr;
    const int*   eis = nullptr;
    const float* Wg[6] = {nullptr, nullptr, nullptr, nullptr, nullptr, nullptr};
    const float* bg[6] = {nullptr, nullptr, nullptr, nullptr, nullptr, nullptr};
    const float* Wlin = nullptr;
    const float* blin = nullptr;
    int wi = 0, bi = 0;
    for (int i = 0; i < n_in; i++) {
        long sz = in_sizes[i];
        void* p = d_in[i];
        if (sz == (long)TT * NN * FF)      xs  = (const float*)p;
        else if (sz == (long)TT * EE)      eas = (const float*)p;
        else if (sz == (long)2 * TT * EE)  eis = (const int*)p;
        else if (sz == (long)NN)           { /* batch: contiguous by construction */ }
        else if (sz == (long)FF * FF && wi < 6) Wg[wi++] = (const float*)p;
        else if (sz == (long)FF && bi < 6)      bg[bi++] = (const float*)p;
        else if (sz == (long)FF * CC)      Wlin = (const float*)p;
        else if (sz == (long)CC)           blin = (const float*)p;
    }
    float* y = (float*)d_out;

    // ARes 40960 + Bring 50688 + z 17408 = 109056 B -> 2 CTAs/SM
    const int SMEM_GRU = ARES_TOT * 4 + BS_TOT * 4 + BM * ZSH * 2;
    cudaFuncSetAttribute(k_gru, cudaFuncAttributeMaxDynamicSharedMemorySize, SMEM_GRU);

    k_init_hout<<<(NN * FF / 4 + 255) / 256, 256>>>();
    k_pack<<<(32768 + 16384 + 384 + 255) / 256, 256>>>(
        Wg[0], bg[0], Wg[1], bg[1], Wg[2], bg[2],
        Wg[3], bg[3], Wg[4], bg[4], Wg[5], bg[5]);
    k_h16<<<(int)(((size_t)TT * NN * FF / 8 + 255) / 256), 256>>>(xs);

    // h-independent pipeline, batched over all 4 timesteps
    k_prep4<<<(TT * NN + 255) / 256, 256>>>();
    k_cnt4<<<dim3((EE + 255) / 256, TT), 256>>>(eis);
    k_scan1<<<dim3(NBLK, TT), 256>>>();
    k_scan2<<<TT, 512>>>();
    k_scan3<<<dim3(NBLK, TT), 256>>>();
    k_fill4<<<dim3((EE + 255) / 256, TT), 256>>>(eas, eis);
    k_deg4<<<(TT * NN + 255) / 256, 256>>>();
    k_norm4<<<(int)(((size_t)TT * EE + 255) / 256), 256>>>();
    k_agg4<<<dim3((NN * 32 + 255) / 256, TT), 256>>>();

    // sequential GRU steps (h dependency)
    for (int t = 0; t < TT; t++)
        k_gru<<<NN / BM, 256, SMEM_GRU>>>(t);

    k_pool<<<BB, 128>>>(Wlin, blin, y);
}

// round 16
// speedup vs baseline: 1.1063x; 1.0688x over previous
#include <cuda_runtime.h>
#include <cuda_fp16.h>
#include <cstdint>

#define NN 113664
#define FF 128
#define EE 909312
#define TT 4
#define BB 1024
#define CC 2
#define NPG 111        // nodes per graph = NN/BB
#define NBLK 444       // NN / 256

// GEMM tiling (fp16 mma.m16n8k16), BM=64 rows/CTA, 256 threads, 2 CTAs/SM
#define BM 64
#define KC 32          // K floats per chunk (16 half2)
#define AS_STR 20      // A row stride in uints -> conflict-free frags
#define BSZ_STR 264    // B k2-row stride GEMM1 (n=256)
#define BSC_STR 136    // B k2-row stride GEMM2 (n=128)
#define ZSH 136        // z fp16 smem stride (halves)
#define AS_STAGE (BM * AS_STR)       // 1280 uints per A chunk
#define BS_STAGE (16 * BSZ_STR)      // 4224 uints per B slot
#define ARES_TOT (8 * AS_STAGE)      // 10240 uints: all 8 A chunks resident
#define BS_TOT (3 * BS_STAGE)        // 12672 uints: 3-slot B ring

// ---------------- device scratch (static: no runtime allocation) ----------------
__device__ float g_dinv[TT * NN];
__device__ int   g_cnt [TT * NN];
__device__ int   g_rowptr[TT * (NN + 1)];
__device__ int   g_cursor[TT * NN];
__device__ int   g_bsum[TT * NBLK];
__device__ int   g_boff[TT * (NBLK + 1)];
__device__ int2  g_cv[TT * EE];          // packed (col, val-bits) per edge
__device__ __half g_xh  [TT * NN * FF];  // fp16 copy of xs
__device__ __half g_axh [TT * NN * FF];  // fp16 aggregated features
__device__ __half g_hh  [NN * FF];       // fp16 hidden state
__device__ __half g_outh[TT * NN * FF];  // fp16 per-step outputs (summed in pool)
__device__ unsigned g_Wzr[128 * 256];   // half2 packed [k2][n]: n<128:z n>=128:r
__device__ unsigned g_Whc[128 * 128];   // half2 packed [k2][n]
__device__ float g_bias_zr[256];
__device__ float g_bias_c[128];

// ---------------- math helpers ----------------
__device__ __forceinline__ float tanh_fast(float x) {
    float y;
    asm("tanh.approx.f32 %0, %1;" : "=f"(y) : "f"(x));
    return y;
}
__device__ __forceinline__ float sigmoid_fast(float x) {
    return 0.5f * tanh_fast(0.5f * x) + 0.5f;
}
__device__ __forceinline__ unsigned pkh2(float a, float b) {
    __half2 h = __float22half2_rn(make_float2(a, b));
    return *reinterpret_cast<unsigned*>(&h);
}
__device__ __forceinline__ void mma_f16(float d[4], const unsigned a[4], const unsigned b[2]) {
    asm volatile(
        "mma.sync.aligned.m16n8k16.row.col.f32.f16.f16.f32 "
        "{%0,%1,%2,%3}, {%4,%5,%6,%7}, {%8,%9}, {%0,%1,%2,%3};"
        : "+f"(d[0]), "+f"(d[1]), "+f"(d[2]), "+f"(d[3])
        : "r"(a[0]), "r"(a[1]), "r"(a[2]), "r"(a[3]), "r"(b[0]), "r"(b[1]));
}
__device__ __forceinline__ uint32_t smem_u32(const void* p) {
    uint32_t a;
    asm("{ .reg .u64 t; cvta.to.shared.u64 t, %1; cvt.u32.u64 %0, t; }" : "=r"(a) : "l"(p));
    return a;
}
__device__ __forceinline__ void cpa16(uint32_t dst, const void* src) {
    asm volatile("cp.async.cg.shared.global [%0], [%1], 16;" :: "r"(dst), "l"(src));
}
#define CP_COMMIT() asm volatile("cp.async.commit_group;" ::: "memory")
#define CP_WAIT(n)  asm volatile("cp.async.wait_group %0;" :: "n"(n) : "memory")

// ---------------- init: hh = eye(N,F) fp16 ----------------
__global__ void k_init_h() {
    int idx = blockIdx.x * blockDim.x + threadIdx.x;   // uint4 index over g_hh
    if (idx >= NN * FF / 8) return;
    int base = idx * 8;
    int row = base >> 7;
    int c0 = base & 127;
    __half h8[8];
#pragma unroll
    for (int u = 0; u < 8; u++) h8[u] = __float2half(0.f);
    if (row < FF && row >= c0 && row < c0 + 8) h8[row - c0] = __float2half(1.f);
    reinterpret_cast<uint4*>(g_hh)[idx] = *reinterpret_cast<uint4*>(h8);
}

// ---------------- xs -> fp16 (all steps); also zeroes g_cnt ----------------
__global__ void k_h16(const float* __restrict__ xs) {
    size_t idx = (size_t)blockIdx.x * blockDim.x + threadIdx.x;
    if (idx >= (size_t)TT * NN * FF / 8) return;
    if (idx < (size_t)TT * NN) g_cnt[idx] = 0;
    const float4* src = reinterpret_cast<const float4*>(xs) + idx * 2;
    float4 v0 = __ldg(src), v1 = __ldg(src + 1);
    uint4 o = make_uint4(pkh2(v0.x, v0.y), pkh2(v0.z, v0.w),
                         pkh2(v1.x, v1.y), pkh2(v1.z, v1.w));
    reinterpret_cast<uint4*>(g_xh)[idx] = o;
}

// ---------------- weight packing: half2 [k2][n] + fused biases ----------------
__global__ void k_pack(const float* __restrict__ Wzi, const float* __restrict__ bzi,
                       const float* __restrict__ Wzh, const float* __restrict__ bzh,
                       const float* __restrict__ Wri, const float* __restrict__ bri,
                       const float* __restrict__ Wrh, const float* __restrict__ brh,
                       const float* __restrict__ Whi, const float* __restrict__ bhi,
                       const float* __restrict__ Whh, const float* __restrict__ bhh) {
    int i = blockIdx.x * blockDim.x + threadIdx.x;
    if (i < 32768) {                       // g_Wzr: [k2=0..127][n=0..255]
        int k2 = i >> 8, n = i & 255;
        int k = 2 * k2;
        float v0, v1;
        if (k < 128) {
            v0 = (n < 128) ? Wzi[k * 128 + n]       : Wri[k * 128 + (n - 128)];
            v1 = (n < 128) ? Wzi[(k + 1) * 128 + n] : Wri[(k + 1) * 128 + (n - 128)];
        } else {
            int kk = k - 128;
            v0 = (n < 128) ? Wzh[kk * 128 + n]       : Wrh[kk * 128 + (n - 128)];
            v1 = (n < 128) ? Wzh[(kk + 1) * 128 + n] : Wrh[(kk + 1) * 128 + (n - 128)];
        }
        g_Wzr[i] = pkh2(v0, v1);
    } else if (i < 32768 + 16384) {        // g_Whc: [k2=0..127][n=0..127]
        int j = i - 32768;
        int k2 = j >> 7, n = j & 127;
        int k = 2 * k2;
        float v0, v1;
        if (k < 128) { v0 = Whi[k * 128 + n]; v1 = Whi[(k + 1) * 128 + n]; }
        else { int kk = k - 128; v0 = Whh[kk * 128 + n]; v1 = Whh[(kk + 1) * 128 + n]; }
        g_Whc[j] = pkh2(v0, v1);
    } else if (i < 32768 + 16384 + 256) {
        int n = i - (32768 + 16384);
        g_bias_zr[n] = (n < 128) ? (bzi[n] + bzh[n]) : (bri[n - 128] + brh[n - 128]);
    } else if (i < 32768 + 16384 + 384) {
        int n = i - (32768 + 16384 + 256);
        g_bias_c[n] = bhi[n] + bhh[n];
    }
}

// ---------------- batched per-step CSR build ----------------
__global__ void k_cnt4(const int* __restrict__ eis) {
    int e = blockIdx.x * blockDim.x + threadIdx.x;
    int t = blockIdx.y;
    if (e >= EE) return;
    int d = eis[(size_t)t * 2 * EE + EE + e];
    atomicAdd(&g_cnt[t * NN + d], 1);
}

__global__ void k_scan1() {
    __shared__ int sh[256];
    int tid = threadIdx.x;
    int t = blockIdx.y;
    sh[tid] = g_cnt[t * NN + blockIdx.x * 256 + tid];
    __syncthreads();
#pragma unroll
    for (int off = 128; off > 0; off >>= 1) {
        if (tid < off) sh[tid] += sh[tid + off];
        __syncthreads();
    }
    if (tid == 0) g_bsum[t * NBLK + blockIdx.x] = sh[0];
}

__global__ void k_scan2() {
    __shared__ int sh[512];
    int tid = threadIdx.x;
    int t = blockIdx.x;
    int v = (tid < NBLK) ? g_bsum[t * NBLK + tid] : 0;
    sh[tid] = v;
    __syncthreads();
#pragma unroll
    for (int off = 1; off < 512; off <<= 1) {
        int u = (tid >= off) ? sh[tid - off] : 0;
        __syncthreads();
        sh[tid] += u;
        __syncthreads();
    }
    if (tid < NBLK) g_boff[t * (NBLK + 1) + tid] = sh[tid] - v;
    if (tid == NBLK - 1) g_boff[t * (NBLK + 1) + NBLK] = sh[tid];
}

__global__ void k_scan3() {
    __shared__ int sh[256];
    int tid = threadIdx.x;
    int t = blockIdx.y;
    int i = blockIdx.x * 256 + tid;
    int c = g_cnt[t * NN + i];
    sh[tid] = c;
    __syncthreads();
#pragma unroll
    for (int off = 1; off < 256; off <<= 1) {
        int u = (tid >= off) ? sh[tid - off] : 0;
        __syncthreads();
        sh[tid] += u;
        __syncthreads();
    }
    int excl = sh[tid] - c + g_boff[t * (NBLK + 1) + blockIdx.x];
    g_rowptr[t * (NN + 1) + i] = excl;
    g_cursor[t * NN + i] = excl;
    if (i == NN - 1) g_rowptr[t * (NN + 1) + NN] = excl + c;
}

__global__ void k_fill4(const float* __restrict__ eas, const int* __restrict__ eis) {
    int e = blockIdx.x * blockDim.x + threadIdx.x;
    int t = blockIdx.y;
    if (e >= EE) return;
    int s = eis[(size_t)t * 2 * EE + e];
    int d = eis[(size_t)t * 2 * EE + EE + e];
    int pos = atomicAdd(&g_cursor[t * NN + d], 1);
    g_cv[(size_t)t * EE + pos] = make_int2(s, __float_as_int(eas[(size_t)t * EE + e]));
}

__global__ void k_deg4() {
    int i = blockIdx.x * blockDim.x + threadIdx.x;
    if (i >= TT * NN) return;
    int t = i / NN;
    int nidx = i - t * NN;
    int beg = g_rowptr[t * (NN + 1) + nidx], end = g_rowptr[t * (NN + 1) + nidx + 1];
    const int2* cv = g_cv + (size_t)t * EE;
    float s = 1.0f;
    for (int j = beg; j < end; j++) s += __int_as_float(cv[j].y);
    g_dinv[i] = rsqrtf(s);
}

// pre-normalize: val[e] *= dinv[col[e]]
__global__ void k_norm4() {
    size_t e = (size_t)blockIdx.x * blockDim.x + threadIdx.x;
    if (e >= (size_t)TT * EE) return;
    int t = (int)(e / EE);
    int2 cv = g_cv[e];
    cv.y = __float_as_int(__int_as_float(cv.y) * g_dinv[t * NN + cv.x]);
    g_cv[e] = cv;
}

// ---------------- sparse aggregate (fp16 gather, lane-parallel edges, 4x MLP) ----------------
__global__ void k_agg4() {
    int gw = (blockIdx.x * blockDim.x + threadIdx.x) >> 5;
    int t = blockIdx.y;
    if (gw >= NN) return;
    int lane = threadIdx.x & 31;

    const __half* x = g_xh + (size_t)t * NN * FF;
    float dinv_d = g_dinv[t * NN + gw];
    float self = dinv_d * dinv_d;

    uint2 raw = __ldg(reinterpret_cast<const uint2*>(x + (size_t)gw * FF) + lane);
    float2 xv0 = __half22float2(*reinterpret_cast<const __half2*>(&raw.x));
    float2 xv1 = __half22float2(*reinterpret_cast<const __half2*>(&raw.y));

    float4 a = make_float4(0.f, 0.f, 0.f, 0.f);
    int beg = g_rowptr[t * (NN + 1) + gw], end = g_rowptr[t * (NN + 1) + gw + 1];
    const int2* cvp = g_cv + (size_t)t * EE;

    for (int base = beg; base < end; base += 32) {
        int j = base + lane;
        int2 cv = (j < end) ? __ldg(cvp + j) : make_int2(0, 0);
        int cnt = min(32, end - base);
        int k = 0;
        for (; k + 4 <= cnt; k += 4) {
            int s0 = __shfl_sync(0xffffffffu, cv.x, k);
            int s1 = __shfl_sync(0xffffffffu, cv.x, k + 1);
            int s2 = __shfl_sync(0xffffffffu, cv.x, k + 2);
            int s3 = __shfl_sync(0xffffffffu, cv.x, k + 3);
            float v0 = __int_as_float(__shfl_sync(0xffffffffu, cv.y, k));
            float v1 = __int_as_float(__shfl_sync(0xffffffffu, cv.y, k + 1));
            float v2 = __int_as_float(__shfl_sync(0xffffffffu, cv.y, k + 2));
            float v3 = __int_as_float(__shfl_sync(0xffffffffu, cv.y, k + 3));
            uint2 r0 = __ldg(reinterpret_cast<const uint2*>(x + (size_t)s0 * FF) + lane);
            uint2 r1 = __ldg(reinterpret_cast<const uint2*>(x + (size_t)s1 * FF) + lane);
            uint2 r2 = __ldg(reinterpret_cast<const uint2*>(x + (size_t)s2 * FF) + lane);
            uint2 r3 = __ldg(reinterpret_cast<const uint2*>(x + (size_t)s3 * FF) + lane);
            float2 f;
            f = __half22float2(*reinterpret_cast<const __half2*>(&r0.x)); a.x += v0 * f.x; a.y += v0 * f.y;
            f = __half22float2(*reinterpret_cast<const __half2*>(&r0.y)); a.z += v0 * f.x; a.w += v0 * f.y;
            f = __half22float2(*reinterpret_cast<const __half2*>(&r1.x)); a.x += v1 * f.x; a.y += v1 * f.y;
            f = __half22float2(*reinterpret_cast<const __half2*>(&r1.y)); a.z += v1 * f.x; a.w += v1 * f.y;
            f = __half22float2(*reinterpret_cast<const __half2*>(&r2.x)); a.x += v2 * f.x; a.y += v2 * f.y;
            f = __half22float2(*reinterpret_cast<const __half2*>(&r2.y)); a.z += v2 * f.x; a.w += v2 * f.y;
            f = __half22float2(*reinterpret_cast<const __half2*>(&r3.x)); a.x += v3 * f.x; a.y += v3 * f.y;
            f = __half22float2(*reinterpret_cast<const __half2*>(&r3.y)); a.z += v3 * f.x; a.w += v3 * f.y;
        }
        for (; k < cnt; k++) {
            int   s = __shfl_sync(0xffffffffu, cv.x, k);
            float v = __int_as_float(__shfl_sync(0xffffffffu, cv.y, k));
            uint2 rw = __ldg(reinterpret_cast<const uint2*>(x + (size_t)s * FF) + lane);
            float2 f0 = __half22float2(*reinterpret_cast<const __half2*>(&rw.x));
            float2 f1 = __half22float2(*reinterpret_cast<const __half2*>(&rw.y));
            a.x += v * f0.x; a.y += v * f0.y; a.z += v * f1.x; a.w += v * f1.y;
        }
    }
    a.x = dinv_d * a.x + self * xv0.x;
    a.y = dinv_d * a.y + self * xv0.y;
    a.z = dinv_d * a.z + self * xv1.x;
    a.w = dinv_d * a.w + self * xv1.y;
    uint2 w;
    w.x = pkh2(a.x, a.y);
    w.y = pkh2(a.z, a.w);
    reinterpret_cast<uint2*>(g_axh + (size_t)t * NN * FF + (size_t)gw * FF)[lane] = w;
}

// ================= Fused GRU step: resident-A + 3-slot B ring (cp.async) =================
__global__ void __launch_bounds__(256, 2) k_gru(int step) {
    extern __shared__ unsigned sm[];
    unsigned* Ares = sm;                                  // 8 x AS_STAGE
    unsigned* Bs = sm + ARES_TOT;                         // 3 x BS_STAGE
    __half* z_h = reinterpret_cast<__half*>(sm + ARES_TOT + BS_TOT);  // [64][ZSH]

    const uint32_t ares_b = smem_u32(Ares);
    const uint32_t bs_b = smem_u32(Bs);

    const __half* axh = g_axh + (size_t)step * NN * FF;
    const int tid = threadIdx.x;
    const int w = tid >> 5, lane = tid & 31;
    const int wm = w & 1, wn = w >> 1;
    const int gid = lane >> 2, tig = lane & 3;
    const int row0 = blockIdx.x * BM;
    const int ar = tid >> 2, aq = tid & 3;

    const uint32_t a_dst0 = ares_b + (uint32_t)(ar * AS_STR + aq * 4) * 4;

    // prologue: group0 = all 8 A chunks + B0; group1 = B1
    {
#pragma unroll
        for (int c = 0; c < 8; c++) {
            const __half* Asrc = ((c < 4) ? axh : g_hh)
                               + (size_t)(row0 + ar) * FF + (c & 3) * KC;
            cpa16(a_dst0 + (uint32_t)(c * AS_STAGE) * 4,
                  reinterpret_cast<const uint4*>(Asrc) + aq);
        }
        const uint4* Bp = reinterpret_cast<const uint4*>(g_Wzr);
#pragma unroll
        for (int t_ = 0; t_ < 4; t_++) {
            int i_ = tid + t_ * 256;
            cpa16(bs_b + (uint32_t)((i_ >> 6) * BSZ_STR + (i_ & 63) * 4) * 4, Bp + i_);
        }
        CP_COMMIT();
        const uint4* Bp1 = reinterpret_cast<const uint4*>(g_Wzr + 4096);
#pragma unroll
        for (int t_ = 0; t_ < 4; t_++) {
            int i_ = tid + t_ * 256;
            cpa16(bs_b + (uint32_t)(BS_STAGE + (i_ >> 6) * BSZ_STR + (i_ & 63) * 4) * 4, Bp1 + i_);
        }
        CP_COMMIT();
    }

    // ---------------- GEMM1: N=256 ----------------
    float acc1[2][8][4];
#pragma unroll
    for (int mt = 0; mt < 2; mt++)
#pragma unroll
        for (int nt = 0; nt < 8; nt++)
#pragma unroll
            for (int q = 0; q < 4; q++) acc1[mt][nt][q] = 0.f;

#pragma unroll
    for (int chunk = 0; chunk < 8; chunk++) {
        if (chunk < 7) CP_WAIT(1); else CP_WAIT(0);
        __syncthreads();
        if (chunk <= 5) {
            int c2 = chunk + 2, s_ = c2 % 3;
            const uint4* Bp = reinterpret_cast<const uint4*>(g_Wzr + (size_t)c2 * 4096);
#pragma unroll
            for (int t_ = 0; t_ < 4; t_++) {
                int i_ = tid + t_ * 256;
                cpa16(bs_b + (uint32_t)(s_ * BS_STAGE + (i_ >> 6) * BSZ_STR + (i_ & 63) * 4) * 4,
                      Bp + i_);
            }
            CP_COMMIT();
        }
        const unsigned* Asp = Ares + chunk * AS_STAGE;
        const unsigned* Bsp = Bs + (chunk % 3) * BS_STAGE;
#pragma unroll
        for (int ks = 0; ks < 2; ks++) {
            int kb = ks * 8;
            unsigned a[2][4];
#pragma unroll
            for (int mt = 0; mt < 2; mt++) {
                int rb = wm * 32 + mt * 16 + gid;
                a[mt][0] = Asp[rb * AS_STR + kb + tig];
                a[mt][1] = Asp[(rb + 8) * AS_STR + kb + tig];
                a[mt][2] = Asp[rb * AS_STR + kb + tig + 4];
                a[mt][3] = Asp[(rb + 8) * AS_STR + kb + tig + 4];
            }
#pragma unroll
            for (int nt = 0; nt < 8; nt++) {
                unsigned b[2];
                int cb = wn * 64 + nt * 8 + gid;
                b[0] = Bsp[(kb + tig) * BSZ_STR + cb];
                b[1] = Bsp[(kb + tig + 4) * BSZ_STR + cb];
                mma_f16(acc1[0][nt], a[0], b);
                mma_f16(acc1[1][nt], a[1], b);
            }
        }
    }
    __syncthreads();   // GEMM1 done: ring free, h region safe to overwrite

    // prefetch GEMM2 B0,B1 (overlaps epilogue1)
    {
        const uint4* Bp = reinterpret_cast<const uint4*>(g_Whc);
#pragma unroll
        for (int t_ = 0; t_ < 2; t_++) {
            int i_ = tid + t_ * 256;
            cpa16(bs_b + (uint32_t)((i_ >> 5) * BSC_STR + (i_ & 31) * 4) * 4, Bp + i_);
        }
        CP_COMMIT();
        const uint4* Bp1 = reinterpret_cast<const uint4*>(g_Whc + 2048);
#pragma unroll
        for (int t_ = 0; t_ < 2; t_++) {
            int i_ = tid + t_ * 256;
            cpa16(bs_b + (uint32_t)(BS_STAGE + (i_ >> 5) * BSC_STR + (i_ & 31) * 4) * 4, Bp1 + i_);
        }
        CP_COMMIT();
    }

    // epilogue1: wn 0,1 -> z (fp16); wn 2,3 -> hr = sig(.)*h, written over h in ARes
#pragma unroll
    for (int mt = 0; mt < 2; mt++) {
#pragma unroll
        for (int nt = 0; nt < 8; nt++) {
            int col = wn * 64 + nt * 8 + 2 * tig;
            int lr1 = wm * 32 + mt * 16 + gid;
            int lr2 = lr1 + 8;
            float b0 = g_bias_zr[col], b1 = g_bias_zr[col + 1];
            if (wn < 2) {
                int n = col;
                *reinterpret_cast<__half2*>(z_h + lr1 * ZSH + n) =
                    __floats2half2_rn(sigmoid_fast(acc1[mt][nt][0] + b0),
                                      sigmoid_fast(acc1[mt][nt][1] + b1));
                *reinterpret_cast<__half2*>(z_h + lr2 * ZSH + n) =
                    __floats2half2_rn(sigmoid_fast(acc1[mt][nt][2] + b0),
                                      sigmoid_fast(acc1[mt][nt][3] + b1));
            } else {
                int n = col - 128;
                int uoff = (4 + (n >> 5)) * AS_STAGE + ((n & 31) >> 1);
                __half2* p1 = reinterpret_cast<__half2*>(&Ares[uoff + lr1 * AS_STR]);
                __half2* p2 = reinterpret_cast<__half2*>(&Ares[uoff + lr2 * AS_STR]);
                float2 h1 = __half22float2(*p1);
                float2 h2 = __half22float2(*p2);
                *p1 = __floats2half2_rn(sigmoid_fast(acc1[mt][nt][0] + b0) * h1.x,
                                        sigmoid_fast(acc1[mt][nt][1] + b1) * h1.y);
                *p2 = __floats2half2_rn(sigmoid_fast(acc1[mt][nt][2] + b0) * h2.x,
                                        sigmoid_fast(acc1[mt][nt][3] + b1) * h2.y);
            }
        }
    }

    // ---------------- GEMM2: N=128, A = ARes (ax chunks 0-3, hr chunks 4-7) ----------------
    float acc[2][4][4];
#pragma unroll
    for (int mt = 0; mt < 2; mt++)
#pragma unroll
        for (int nt = 0; nt < 4; nt++)
#pragma unroll
            for (int q = 0; q < 4; q++) acc[mt][nt][q] = 0.f;

#pragma unroll
    for (int chunk = 0; chunk < 8; chunk++) {
        if (chunk < 7) CP_WAIT(1); else CP_WAIT(0);
        __syncthreads();   // first iteration also publishes epilogue1's hr/z writes
        if (chunk <= 5) {
            int c2 = chunk + 2, s_ = c2 % 3;
            const uint4* Bp = reinterpret_cast<const uint4*>(g_Whc + (size_t)c2 * 2048);
#pragma unroll
            for (int t_ = 0; t_ < 2; t_++) {
                int i_ = tid + t_ * 256;
                cpa16(bs_b + (uint32_t)(s_ * BS_STAGE + (i_ >> 5) * BSC_STR + (i_ & 31) * 4) * 4,
                      Bp + i_);
            }
            CP_COMMIT();
        }
        const unsigned* Asp = Ares + chunk * AS_STAGE;
        const unsigned* Bsp = Bs + (chunk % 3) * BS_STAGE;
#pragma unroll
        for (int ks = 0; ks < 2; ks++) {
            int kb = ks * 8;
            unsigned a[2][4];
#pragma unroll
            for (int mt = 0; mt < 2; mt++) {
                int rb = wm * 32 + mt * 16 + gid;
                a[mt][0] = Asp[rb * AS_STR + kb + tig];
                a[mt][1] = Asp[(rb + 8) * AS_STR + kb + tig];
                a[mt][2] = Asp[rb * AS_STR + kb + tig + 4];
                a[mt][3] = Asp[(rb + 8) * AS_STR + kb + tig + 4];
            }
#pragma unroll
            for (int nt = 0; nt < 4; nt++) {
                unsigned b[2];
                int cb = wn * 32 + nt * 8 + gid;
                b[0] = Bsp[(kb + tig) * BSC_STR + cb];
                b[1] = Bsp[(kb + tig + 4) * BSC_STR + cb];
                mma_f16(acc[0][nt], a[0], b);
                mma_f16(acc[1][nt], a[1], b);
            }
        }
    }

    // epilogue2: cand = tanh(acc + bias); hn = (1-z)*hr; hh = hn; outh[step] = hn + z*cand
    __half* outp = g_outh + (size_t)step * NN * FF;
#pragma unroll
    for (int mt = 0; mt < 2; mt++) {
#pragma unroll
        for (int nt = 0; nt < 4; nt++) {
            int n = wn * 32 + nt * 8 + 2 * tig;
            float b0 = g_bias_c[n], b1 = g_bias_c[n + 1];
            int uoff = (4 + (n >> 5)) * AS_STAGE + ((n & 31) >> 1);
#pragma unroll
            for (int half = 0; half < 2; half++) {
                int lr = wm * 32 + mt * 16 + gid + half * 8;
                int row = row0 + lr;
                float c0 = tanh_fast(acc[mt][nt][half * 2]     + b0);
                float c1 = tanh_fast(acc[mt][nt][half * 2 + 1] + b1);
                float2 zv = __half22float2(
                    *reinterpret_cast<const __half2*>(z_h + lr * ZSH + n));
                float2 hr = __half22float2(
                    *reinterpret_cast<const __half2*>(&Ares[uoff + lr * AS_STR]));
                float2 hn = make_float2((1.f - zv.x) * hr.x, (1.f - zv.y) * hr.y);
                size_t idx = (size_t)row * FF + n;
                *reinterpret_cast<__half2*>(g_hh + idx) = __floats2half2_rn(hn.x, hn.y);
                *reinterpret_cast<__half2*>(outp + idx) =
                    __floats2half2_rn(hn.x + zv.x * c0, hn.y + zv.y * c1);
            }
        }
    }
}

// ---------------- pooling + classifier (sums 4 fp16 out slices) ----------------
__global__ void k_pool(const float* __restrict__ Wlin, const float* __restrict__ blin,
                       float* __restrict__ y) {
    int g = blockIdx.x;
    int f = threadIdx.x;
    float s = 0.f;
#pragma unroll
    for (int t = 0; t < TT; t++) {
        const __half* base = g_outh + ((size_t)t * NN + (size_t)g * NPG) * FF + f;
#pragma unroll 4
        for (int n = 0; n < NPG; n++) s += __half2float(base[(size_t)n * FF]);
    }
    s *= (1.0f / (float)NPG);
    float p0 = s * __ldg(Wlin + 2 * f);
    float p1 = s * __ldg(Wlin + 2 * f + 1);
#pragma unroll
    for (int off = 16; off > 0; off >>= 1) {
        p0 += __shfl_down_sync(0xffffffffu, p0, off);
        p1 += __shfl_down_sync(0xffffffffu, p1, off);
    }
    __shared__ float r0s[4], r1s[4];
    int w = f >> 5, lane = f & 31;
    if (lane == 0) { r0s[w] = p0; r1s[w] = p1; }
    __syncthreads();
    if (f == 0) {
        y[2 * g]     = r0s[0] + r0s[1] + r0s[2] + r0s[3] + __ldg(blin);
        y[2 * g + 1] = r1s[0] + r1s[1] + r1s[2] + r1s[3] + __ldg(blin + 1);
    }
}

// ---------------- launch ----------------
extern "C" void kernel_launch(void* const* d_in, const int* in_sizes, int n_in,
                              void* d_out, int out_size) {
    const float* xs = nullptr;
    const float* eas = nullptr;
    const int*   eis = nullptr;
    const float* Wg[6] = {nullptr, nullptr, nullptr, nullptr, nullptr, nullptr};
    const float* bg[6] = {nullptr, nullptr, nullptr, nullptr, nullptr, nullptr};
    const float* Wlin = nullptr;
    const float* blin = nullptr;
    int wi = 0, bi = 0;
    for (int i = 0; i < n_in; i++) {
        long sz = in_sizes[i];
        void* p = d_in[i];
        if (sz == (long)TT * NN * FF)      xs  = (const float*)p;
        else if (sz == (long)TT * EE)      eas = (const float*)p;
        else if (sz == (long)2 * TT * EE)  eis = (const int*)p;
        else if (sz == (long)NN)           { /* batch: contiguous by construction */ }
        else if (sz == (long)FF * FF && wi < 6) Wg[wi++] = (const float*)p;
        else if (sz == (long)FF && bi < 6)      bg[bi++] = (const float*)p;
        else if (sz == (long)FF * CC)      Wlin = (const float*)p;
        else if (sz == (long)CC)           blin = (const float*)p;
    }
    float* y = (float*)d_out;

    // ARes 40960 + Bring 50688 + z 17408 = 109056 B -> 2 CTAs/SM
    const int SMEM_GRU = ARES_TOT * 4 + BS_TOT * 4 + BM * ZSH * 2;
    cudaFuncSetAttribute(k_gru, cudaFuncAttributeMaxDynamicSharedMemorySize, SMEM_GRU);

    k_init_h<<<(NN * FF / 8 + 255) / 256, 256>>>();
    k_pack<<<(32768 + 16384 + 384 + 255) / 256, 256>>>(
        Wg[0], bg[0], Wg[1], bg[1], Wg[2], bg[2],
        Wg[3], bg[3], Wg[4], bg[4], Wg[5], bg[5]);
    k_h16<<<(int)(((size_t)TT * NN * FF / 8 + 255) / 256), 256>>>(xs);   // also zeroes g_cnt

    // h-independent pipeline, batched over all 4 timesteps
    k_cnt4<<<dim3((EE + 255) / 256, TT), 256>>>(eis);
    k_scan1<<<dim3(NBLK, TT), 256>>>();
    k_scan2<<<TT, 512>>>();
    k_scan3<<<dim3(NBLK, TT), 256>>>();
    k_fill4<<<dim3((EE + 255) / 256, TT), 256>>>(eas, eis);
    k_deg4<<<(TT * NN + 255) / 256, 256>>>();
    k_norm4<<<(int)(((size_t)TT * EE + 255) / 256), 256>>>();
    k_agg4<<<dim3((NN * 32 + 255) / 256, TT), 256>>>();

    // sequential GRU steps (h dependency)
    for (int t = 0; t < TT; t++)
        k_gru<<<NN / BM, 256, SMEM_GRU>>>(t);

    k_pool<<<BB, 128>>>(Wlin, blin, y);
}